// round 12
// baseline (speedup 1.0000x reference)
#include <cuda_runtime.h>
#include <math.h>
#include <stdint.h>

#define BSZ 4
#define CHN 256
#define PHW 32
#define NPIX (BSZ*PHW*PHW)     // 4096
#define NFULL (BSZ*128*128)    // 65536

// ---- scratch: static device globals (no allocation) ----
__device__ __align__(16) float g_pool_q[BSZ*CHN*PHW*PHW];
__device__ __align__(16) float g_pool_s[BSZ*CHN*PHW*PHW];
__device__ __align__(16) float g_qin [NPIX*CHN];
__device__ __align__(16) float g_sin [NPIX*CHN];
__device__ __align__(16) float g_Qp  [NPIX*CHN];
__device__ __align__(16) float g_Kp  [NPIX*CHN];
__device__ __align__(16) float g_Vn  [NPIX*CHN];
__device__ __align__(16) float g_KV  [BSZ*8*32*32];
__device__ __align__(16) float g_Ksum[BSZ*8*32];
__device__ __align__(16) float g_msg [NPIX*CHN];
__device__ __align__(16) float g_msg2[NPIX*CHN];
__device__ __align__(16) float g_T   [NPIX*512];
__device__ __align__(16) float g_h   [33554432];   // 65536 x 512 relu acts

// ---- packed f32x2 helpers ----
__device__ __forceinline__ unsigned long long pack2(float x){
    unsigned long long r; asm("mov.b64 %0, {%1, %1};" : "=l"(r) : "f"(x)); return r;
}
__device__ __forceinline__ void ffma2(unsigned long long& d, unsigned long long a, unsigned long long b){
    asm("fma.rn.f32x2 %0, %1, %2, %0;" : "+l"(d) : "l"(a), "l"(b));
}
__device__ __forceinline__ float2 unpack2(unsigned long long v){
    float2 r; asm("mov.b64 {%0, %1}, %2;" : "=f"(r.x), "=f"(r.y) : "l"(v)); return r;
}

// ---- 1) 4x4 max pool, NCHW -> coarse NCHW ----
__global__ void pool_kernel(const float* __restrict__ x, const float* __restrict__ src){
    int warp = (blockIdx.x*blockDim.x + threadIdx.x) >> 5;  // (b*256+c)*32 + ph
    int lane = threadIdx.x & 31;                            // pw
    const float* in  = blockIdx.y ? src : x;
    float*       out = blockIdx.y ? g_pool_s : g_pool_q;
    int bc = warp >> 5, ph = warp & 31;
    const float* p = in + (size_t)bc*16384 + ph*4*128 + lane*4;
    float m = -INFINITY;
    #pragma unroll
    for (int r = 0; r < 4; r++){
        float4 v = *(const float4*)(p + r*128);
        m = fmaxf(m, fmaxf(fmaxf(v.x,v.y), fmaxf(v.z,v.w)));
    }
    out[bc*1024 + ph*32 + lane] = m;
}

// ---- 2) LayerNorm over C + transpose to pixel-major ----
__global__ void ln1_kernel(const float* __restrict__ g, const float* __restrict__ bta){
    int warp = (blockIdx.x*blockDim.x + threadIdx.x) >> 5;  // pixel
    int lane = threadIdx.x & 31;
    const float* pool = blockIdx.y ? g_pool_s : g_pool_q;
    float*       out  = blockIdx.y ? g_sin    : g_qin;
    int b = warp >> 10, l = warp & 1023;
    const float* base = pool + (size_t)b*CHN*1024 + l;
    float v[8]; float s = 0.f, sq = 0.f;
    #pragma unroll
    for (int i = 0; i < 8; i++){
        v[i] = base[(size_t)(lane + i*32)*1024];
        s += v[i]; sq += v[i]*v[i];
    }
    #pragma unroll
    for (int o = 16; o; o >>= 1){
        s  += __shfl_xor_sync(0xffffffffu, s,  o);
        sq += __shfl_xor_sync(0xffffffffu, sq, o);
    }
    float mean = s * (1.f/256.f);
    float rstd = rsqrtf(sq*(1.f/256.f) - mean*mean + 1e-5f);
    #pragma unroll
    for (int i = 0; i < 8; i++){
        int c = lane + i*32;
        out[(size_t)warp*CHN + c] = (v[i]-mean)*rstd*g[c] + bta[c];
    }
}

// ---- generic FFMA2 GEMM, 128x128 tile: C = A[M,K]@B[K,N]; EPI 0=none 1=elu+1 2=*scl ----
template<int EPI>
__global__ __launch_bounds__(256, 2) void gemm128(const float* __restrict__ A,
                                                  const float* __restrict__ B,
                                                  float* __restrict__ C,
                                                  int K, int N, float scl){
    __shared__ __align__(16) float As[8][132];
    __shared__ __align__(16) float Bs[8][128];
    int t = threadIdx.x;
    int m0 = blockIdx.x*128, n0 = blockIdx.y*128;
    int tr = t >> 4, tc = t & 15;
    unsigned long long acc[8][4];
    #pragma unroll
    for (int i = 0; i < 8; i++){ acc[i][0]=0; acc[i][1]=0; acc[i][2]=0; acc[i][3]=0; }

    for (int k0 = 0; k0 < K; k0 += 8){
        #pragma unroll
        for (int i = 0; i < 4; i++){
            int e = t + i*256;
            As[e & 7][e >> 3] = A[(size_t)(m0 + (e>>3))*K + k0 + (e&7)];
            Bs[e >> 7][e & 127] = B[(size_t)(k0 + (e>>7))*N + n0 + (e&127)];
        }
        __syncthreads();
        #pragma unroll
        for (int kk = 0; kk < 8; kk++){
            float4 a0 = *(const float4*)&As[kk][tr*4];
            float4 a1 = *(const float4*)&As[kk][64 + tr*4];
            ulonglong2 b0 = *(const ulonglong2*)&Bs[kk][tc*4];
            ulonglong2 b1 = *(const ulonglong2*)&Bs[kk][64 + tc*4];
            float a[8] = {a0.x,a0.y,a0.z,a0.w,a1.x,a1.y,a1.z,a1.w};
            #pragma unroll
            for (int i = 0; i < 8; i++){
                unsigned long long ap = pack2(a[i]);
                ffma2(acc[i][0], ap, b0.x); ffma2(acc[i][1], ap, b0.y);
                ffma2(acc[i][2], ap, b1.x); ffma2(acc[i][3], ap, b1.y);
            }
        }
        __syncthreads();
    }
    #pragma unroll
    for (int i = 0; i < 8; i++){
        int m = m0 + (i < 4 ? tr*4 + i : 64 + tr*4 + (i-4));
        float2 p0 = unpack2(acc[i][0]), p1 = unpack2(acc[i][1]);
        float2 p2 = unpack2(acc[i][2]), p3 = unpack2(acc[i][3]);
        float o[8] = {p0.x,p0.y,p1.x,p1.y,p2.x,p2.y,p3.x,p3.y};
        #pragma unroll
        for (int j = 0; j < 8; j++){
            if (EPI == 1) o[j] = (o[j] > 0.f) ? o[j] + 1.f : expf(o[j]);
            if (EPI == 2) o[j] = o[j] * scl;
        }
        float4 s0 = {o[0],o[1],o[2],o[3]}, s1 = {o[4],o[5],o[6],o[7]};
        *(float4*)&C[(size_t)m*N + n0 + tc*4]      = s0;
        *(float4*)&C[(size_t)m*N + n0 + 64 + tc*4] = s1;
    }
}

// ---- 3) KV[b,h,d,v] = sum_s Kp*Vn ; Ksum[b,h,d] = sum_s Kp ----
__global__ void attn_kv_kernel(){
    __shared__ __align__(16) float Ks[64][32];
    __shared__ __align__(16) float Vs[64][32];
    int t = threadIdx.x;
    int b = blockIdx.x >> 3, h = blockIdx.x & 7;
    int d = t >> 3, vg = (t & 7) * 4;
    float4 acc = {0.f,0.f,0.f,0.f};
    float ks = 0.f;
    for (int s0 = 0; s0 < 1024; s0 += 64){
        #pragma unroll
        for (int i = 0; i < 8; i++){
            int e = t + i*256;
            int s_ = e >> 5, d_ = e & 31;
            size_t gi = (size_t)(b*1024 + s0 + s_)*256 + h*32 + d_;
            Ks[s_][d_] = g_Kp[gi];
            Vs[s_][d_] = g_Vn[gi];
        }
        __syncthreads();
        #pragma unroll 8
        for (int s_ = 0; s_ < 64; s_++){
            float kd = Ks[s_][d];
            float4 v = *(const float4*)&Vs[s_][vg];
            acc.x += kd*v.x; acc.y += kd*v.y; acc.z += kd*v.z; acc.w += kd*v.w;
            ks += kd;
        }
        __syncthreads();
    }
    *(float4*)&g_KV[(size_t)((blockIdx.x*32 + d)*32 + vg)] = acc;
    if ((t & 7) == 0) g_Ksum[blockIdx.x*32 + d] = ks;
}

// ---- 4) msg = (Qp@KV) * L / (Qp.Ksum + eps) ----
__global__ void attn_msg_kernel(){
    __shared__ float KVs[8192];
    __shared__ float Ksums[256];
    int t = threadIdx.x;
    int p = blockIdx.x*8 + (t >> 5);   // 8 pixels/block, never crosses batch
    int lane = t & 31;
    int b = p >> 10;
    #pragma unroll
    for (int i = 0; i < 32; i++) KVs[t + i*256] = g_KV[b*8192 + t + i*256];
    if (t < 256) Ksums[t] = g_Ksum[b*256 + t];
    __syncthreads();
    #pragma unroll
    for (int h = 0; h < 8; h++){
        float qd = g_Qp[(size_t)p*256 + h*32 + lane];
        float zd = qd * Ksums[h*32 + lane];
        #pragma unroll
        for (int o = 16; o; o >>= 1) zd += __shfl_xor_sync(0xffffffffu, zd, o);
        float z = 1024.f / (zd + 1e-6f);
        float a = 0.f;
        #pragma unroll
        for (int dd = 0; dd < 32; dd++)
            a += __shfl_sync(0xffffffffu, qd, dd) * KVs[(h*32 + dd)*32 + lane];
        g_msg[(size_t)p*256 + h*32 + lane] = a * z;
    }
}

// ---- 5) MLP1: g_h = relu(x_nhwc @ W1[:256] + bilinear_up(T)) ----
__global__ __launch_bounds__(256, 2) void mlp1_kernel(const float* __restrict__ x,
                                                      const float* __restrict__ w1){
    __shared__ __align__(16) float As[8][132];
    __shared__ __align__(16) float Bs[8][128];
    __shared__ __align__(16) float Tsm[2][32][128];
    int t = threadIdx.x;
    int row = blockIdx.x;            // b*128 + hh
    int b = row >> 7, hh = row & 127;
    int n0 = blockIdx.y * 128;
    int tr = t >> 4, tc = t & 15;
    const float* xb = x + (size_t)b*4194304 + hh*128;
    unsigned long long acc[8][4];
    #pragma unroll
    for (int i = 0; i < 8; i++){ acc[i][0]=0; acc[i][1]=0; acc[i][2]=0; acc[i][3]=0; }

    for (int k0 = 0; k0 < 256; k0 += 8){
        #pragma unroll
        for (int i = 0; i < 4; i++){
            int e = t + i*256;
            int ma = e & 127, ka = e >> 7;
            As[ka][ma] = xb[(size_t)(k0+ka)*16384 + ma];     // A[ww][c]
            Bs[ka][ma] = w1[(size_t)(k0+ka)*512 + n0 + ma];
        }
        __syncthreads();
        #pragma unroll
        for (int kk = 0; kk < 8; kk++){
            float4 a0 = *(const float4*)&As[kk][tr*4];
            float4 a1 = *(const float4*)&As[kk][64 + tr*4];
            ulonglong2 b0 = *(const ulonglong2*)&Bs[kk][tc*4];
            ulonglong2 b1 = *(const ulonglong2*)&Bs[kk][64 + tc*4];
            float a[8] = {a0.x,a0.y,a0.z,a0.w,a1.x,a1.y,a1.z,a1.w};
            #pragma unroll
            for (int i = 0; i < 8; i++){
                unsigned long long ap = pack2(a[i]);
                ffma2(acc[i][0], ap, b0.x); ffma2(acc[i][1], ap, b0.y);
                ffma2(acc[i][2], ap, b1.x); ffma2(acc[i][3], ap, b1.y);
            }
        }
        __syncthreads();
    }

    // stage the two coarse-T rows needed by this image row (fixed y per block)
    float sy  = hh*0.25f - 0.375f;
    float y0f = floorf(sy);
    float fy  = sy - y0f;
    int y0 = max(0, min(31, (int)y0f));
    int y1 = max(0, min(31, (int)y0f + 1));
    #pragma unroll
    for (int i = 0; i < 32; i++){
        int e = t + i*256;
        int n_ = e & 127, xx = (e >> 7) & 31, yy = e >> 12;
        int ysrc = yy ? y1 : y0;
        Tsm[yy][xx][n_] = g_T[(size_t)((b*32 + ysrc)*32 + xx)*512 + n0 + n_];
    }
    __syncthreads();

    float* hout = g_h + (size_t)row*128*512 + n0;
    #pragma unroll
    for (int i = 0; i < 8; i++){
        int ww = (i < 4 ? tr*4 + i : 64 + tr*4 + (i-4));
        float sx  = ww*0.25f - 0.375f;
        float x0f = floorf(sx);
        float fx  = sx - x0f;
        int x0 = max(0, min(31, (int)x0f));
        int x1 = max(0, min(31, (int)x0f + 1));
        float2 p0 = unpack2(acc[i][0]), p1 = unpack2(acc[i][1]);
        float2 p2 = unpack2(acc[i][2]), p3 = unpack2(acc[i][3]);
        float v[8] = {p0.x,p0.y,p1.x,p1.y,p2.x,p2.y,p3.x,p3.y};
        float o[8];
        #pragma unroll
        for (int jj = 0; jj < 8; jj++){
            int n_ = (jj < 4 ? tc*4 + jj : 64 + tc*4 + (jj-4));
            float up = (1.f-fy)*((1.f-fx)*Tsm[0][x0][n_] + fx*Tsm[0][x1][n_])
                     +       fy*((1.f-fx)*Tsm[1][x0][n_] + fx*Tsm[1][x1][n_]);
            o[jj] = fmaxf(v[jj] + up, 0.f);
        }
        float4 s0 = {o[0],o[1],o[2],o[3]}, s1 = {o[4],o[5],o[6],o[7]};
        *(float4*)&hout[(size_t)ww*512 + tc*4]      = s0;
        *(float4*)&hout[(size_t)ww*512 + 64 + tc*4] = s1;
    }
}

// ---- 6) MLP2: out = x + LN(g_h @ W2), fused NCHW store ----
__global__ __launch_bounds__(256, 2) void mlp2_kernel(const float* __restrict__ x,
                                                      const float* __restrict__ w2,
                                                      const float* __restrict__ g2,
                                                      const float* __restrict__ b2,
                                                      float* __restrict__ out){
    __shared__ __align__(16) float As[8][68];
    __shared__ __align__(16) float Bs[8][256];
    int t = threadIdx.x;
    int w0  = (blockIdx.x & 1) * 64;
    int row = blockIdx.x >> 1;       // b*128 + hh
    int b = row >> 7, hh = row & 127;
    int tr = t >> 5, tc = t & 31;    // warp == tr; warp covers all 256 cols
    const float* hrow = g_h + ((size_t)row*128 + w0)*512;
    unsigned long long acc[8][4];
    #pragma unroll
    for (int i = 0; i < 8; i++){ acc[i][0]=0; acc[i][1]=0; acc[i][2]=0; acc[i][3]=0; }

    for (int k0 = 0; k0 < 512; k0 += 8){
        {
            int e = t;
            As[e & 7][e >> 3] = hrow[(size_t)(e>>3)*512 + k0 + (e&7)];
            e = t + 256;
            As[e & 7][e >> 3] = hrow[(size_t)(e>>3)*512 + k0 + (e&7)];
        }
        #pragma unroll
        for (int i = 0; i < 8; i++){
            int e = t + i*256;
            Bs[e >> 8][e & 255] = w2[(size_t)(k0 + (e>>8))*256 + (e&255)];
        }
        __syncthreads();
        #pragma unroll
        for (int kk = 0; kk < 8; kk++){
            float4 a0 = *(const float4*)&As[kk][tr*4];
            float4 a1 = *(const float4*)&As[kk][32 + tr*4];
            ulonglong2 bb0 = *(const ulonglong2*)&Bs[kk][tc*4];
            ulonglong2 bb1 = *(const ulonglong2*)&Bs[kk][128 + tc*4];
            float a[8] = {a0.x,a0.y,a0.z,a0.w,a1.x,a1.y,a1.z,a1.w};
            #pragma unroll
            for (int i = 0; i < 8; i++){
                unsigned long long ap = pack2(a[i]);
                ffma2(acc[i][0], ap, bb0.x); ffma2(acc[i][1], ap, bb0.y);
                ffma2(acc[i][2], ap, bb1.x); ffma2(acc[i][3], ap, bb1.y);
            }
        }
        __syncthreads();
    }

    // LN stats per pixel (warp reduction over the 256 cols it owns)
    float s[8], sq[8];
    #pragma unroll
    for (int i = 0; i < 8; i++){ s[i]=0.f; sq[i]=0.f; }
    #pragma unroll
    for (int i = 0; i < 8; i++)
        #pragma unroll
        for (int j = 0; j < 4; j++){
            float2 p = unpack2(acc[i][j]);
            s[i]  += p.x + p.y;
            sq[i] += p.x*p.x + p.y*p.y;
        }
    #pragma unroll
    for (int o = 16; o; o >>= 1)
        #pragma unroll
        for (int i = 0; i < 8; i++){
            s[i]  += __shfl_xor_sync(0xffffffffu, s[i],  o);
            sq[i] += __shfl_xor_sync(0xffffffffu, sq[i], o);
        }
    float mean[8], rstd[8];
    #pragma unroll
    for (int i = 0; i < 8; i++){
        mean[i] = s[i] * (1.f/256.f);
        rstd[i] = rsqrtf(sq[i]*(1.f/256.f) - mean[i]*mean[i] + 1e-5f);
    }

    #pragma unroll
    for (int jj = 0; jj < 8; jj++){
        int n  = (jj < 4 ? tc*4 + jj : 128 + tc*4 + (jj-4));
        int pi = (jj < 4 ? (jj >> 1) : 2 + ((jj-4) >> 1));
        int half = jj & 1;
        float gn = g2[n], bn = b2[n];
        size_t base = ((size_t)(b*256 + n)*128 + hh)*128 + w0;
        float4 x0v = *(const float4*)&x[base + tr*4];
        float4 x1v = *(const float4*)&x[base + 32 + tr*4];
        float vv[8];
        #pragma unroll
        for (int i = 0; i < 8; i++){
            float2 p = unpack2(acc[i][pi]);
            float val = half ? p.y : p.x;
            vv[i] = (val - mean[i]) * rstd[i] * gn + bn;
        }
        float4 o0 = {x0v.x + vv[0], x0v.y + vv[1], x0v.z + vv[2], x0v.w + vv[3]};
        float4 o1 = {x1v.x + vv[4], x1v.y + vv[5], x1v.z + vv[6], x1v.w + vv[7]};
        *(float4*)&out[base + tr*4]      = o0;
        *(float4*)&out[base + 32 + tr*4] = o1;
    }
}

// ---- launch ----
extern "C" void kernel_launch(void* const* d_in, const int* in_sizes, int n_in,
                              void* d_out, int out_size){
    const float* x   = (const float*)d_in[0];
    const float* src = (const float*)d_in[1];
    const float* n1g = (const float*)d_in[2];
    const float* n1b = (const float*)d_in[3];
    const float* wq  = (const float*)d_in[4];
    const float* wk  = (const float*)d_in[5];
    const float* wv  = (const float*)d_in[6];
    const float* wm  = (const float*)d_in[7];
    const float* w1  = (const float*)d_in[8];
    const float* w2  = (const float*)d_in[9];
    const float* n2g = (const float*)d_in[10];
    const float* n2b = (const float*)d_in[11];
    float* out = (float*)d_out;

    float *p_qin, *p_sin, *p_Qp, *p_Kp, *p_Vn, *p_msg, *p_msg2, *p_T;
    cudaGetSymbolAddress((void**)&p_qin,  g_qin);
    cudaGetSymbolAddress((void**)&p_sin,  g_sin);
    cudaGetSymbolAddress((void**)&p_Qp,   g_Qp);
    cudaGetSymbolAddress((void**)&p_Kp,   g_Kp);
    cudaGetSymbolAddress((void**)&p_Vn,   g_Vn);
    cudaGetSymbolAddress((void**)&p_msg,  g_msg);
    cudaGetSymbolAddress((void**)&p_msg2, g_msg2);
    cudaGetSymbolAddress((void**)&p_T,    g_T);

    pool_kernel<<<dim3(4096,2), 256>>>(x, src);
    ln1_kernel<<<dim3(512,2), 256>>>(n1g, n1b);
    gemm128<1><<<dim3(32,2), 256>>>(p_qin, wq, p_Qp, 256, 256, 0.f);
    gemm128<1><<<dim3(32,2), 256>>>(p_sin, wk, p_Kp, 256, 256, 0.f);
    gemm128<2><<<dim3(32,2), 256>>>(p_sin, wv, p_Vn, 256, 256, 1.f/1024.f);
    attn_kv_kernel<<<32, 256>>>();
    attn_msg_kernel<<<512, 256>>>();
    gemm128<0><<<dim3(32,2), 256>>>(p_msg, wm, p_msg2, 256, 256, 0.f);
    gemm128<0><<<dim3(32,4), 256>>>(p_msg2, w1 + 256*512, p_T, 256, 512, 0.f);
    mlp1_kernel<<<dim3(512,4), 256>>>(x, w1);
    mlp2_kernel<<<1024, 256>>>(x, w2, n2g, n2b, out);
}

// round 13
// speedup vs baseline: 1.0097x; 1.0097x over previous
#include <cuda_runtime.h>
#include <math.h>
#include <stdint.h>

#define BSZ 4
#define CHN 256
#define PHW 32
#define NPIX (BSZ*PHW*PHW)     // 4096
#define NFULL (BSZ*128*128)    // 65536

// ---- scratch: static device globals (no allocation) ----
__device__ __align__(16) float g_pool_q[BSZ*CHN*PHW*PHW];
__device__ __align__(16) float g_pool_s[BSZ*CHN*PHW*PHW];
__device__ __align__(16) float g_qin [NPIX*CHN];
__device__ __align__(16) float g_sin [NPIX*CHN];
__device__ __align__(16) float g_Qp  [NPIX*CHN];
__device__ __align__(16) float g_Kp  [NPIX*CHN];
__device__ __align__(16) float g_Vn  [NPIX*CHN];
__device__ __align__(16) float g_KV  [BSZ*8*32*32];
__device__ __align__(16) float g_Ksum[BSZ*8*32];
__device__ __align__(16) float g_msg [NPIX*CHN];
__device__ __align__(16) float g_msg2[NPIX*CHN];
__device__ __align__(16) float g_T   [NPIX*512];
__device__ __align__(16) float g_h   [33554432];   // 65536 x 512 relu acts

// ---- packed f32x2 helpers ----
__device__ __forceinline__ unsigned long long pack2(float x){
    unsigned long long r; asm("mov.b64 %0, {%1, %1};" : "=l"(r) : "f"(x)); return r;
}
__device__ __forceinline__ void ffma2(unsigned long long& d, unsigned long long a, unsigned long long b){
    asm("fma.rn.f32x2 %0, %1, %2, %0;" : "+l"(d) : "l"(a), "l"(b));
}
__device__ __forceinline__ float2 unpack2(unsigned long long v){
    float2 r; asm("mov.b64 {%0, %1}, %2;" : "=f"(r.x), "=f"(r.y) : "l"(v)); return r;
}

// ---- 1) 4x4 max pool, NCHW -> coarse NCHW ----
__global__ void pool_kernel(const float* __restrict__ x, const float* __restrict__ src){
    int warp = (blockIdx.x*blockDim.x + threadIdx.x) >> 5;  // (b*256+c)*32 + ph
    int lane = threadIdx.x & 31;                            // pw
    const float* in  = blockIdx.y ? src : x;
    float*       out = blockIdx.y ? g_pool_s : g_pool_q;
    int bc = warp >> 5, ph = warp & 31;
    const float* p = in + (size_t)bc*16384 + ph*4*128 + lane*4;
    float m = -INFINITY;
    #pragma unroll
    for (int r = 0; r < 4; r++){
        float4 v = *(const float4*)(p + r*128);
        m = fmaxf(m, fmaxf(fmaxf(v.x,v.y), fmaxf(v.z,v.w)));
    }
    out[bc*1024 + ph*32 + lane] = m;
}

// ---- 2) LayerNorm over C + transpose to pixel-major ----
__global__ void ln1_kernel(const float* __restrict__ g, const float* __restrict__ bta){
    int warp = (blockIdx.x*blockDim.x + threadIdx.x) >> 5;  // pixel
    int lane = threadIdx.x & 31;
    const float* pool = blockIdx.y ? g_pool_s : g_pool_q;
    float*       out  = blockIdx.y ? g_sin    : g_qin;
    int b = warp >> 10, l = warp & 1023;
    const float* base = pool + (size_t)b*CHN*1024 + l;
    float v[8]; float s = 0.f, sq = 0.f;
    #pragma unroll
    for (int i = 0; i < 8; i++){
        v[i] = base[(size_t)(lane + i*32)*1024];
        s += v[i]; sq += v[i]*v[i];
    }
    #pragma unroll
    for (int o = 16; o; o >>= 1){
        s  += __shfl_xor_sync(0xffffffffu, s,  o);
        sq += __shfl_xor_sync(0xffffffffu, sq, o);
    }
    float mean = s * (1.f/256.f);
    float rstd = rsqrtf(sq*(1.f/256.f) - mean*mean + 1e-5f);
    #pragma unroll
    for (int i = 0; i < 8; i++){
        int c = lane + i*32;
        out[(size_t)warp*CHN + c] = (v[i]-mean)*rstd*g[c] + bta[c];
    }
}

// ---- generic FFMA2 GEMM, 128x128 tile: C = A[M,K]@B[K,N]; EPI 0=none 1=elu+1 2=*scl ----
template<int EPI>
__global__ __launch_bounds__(256, 2) void gemm128(const float* __restrict__ A,
                                                  const float* __restrict__ B,
                                                  float* __restrict__ C,
                                                  int K, int N, float scl){
    __shared__ __align__(16) float As[8][132];
    __shared__ __align__(16) float Bs[8][128];
    int t = threadIdx.x;
    int m0 = blockIdx.x*128, n0 = blockIdx.y*128;
    int tr = t >> 4, tc = t & 15;
    unsigned long long acc[8][4];
    #pragma unroll
    for (int i = 0; i < 8; i++){ acc[i][0]=0; acc[i][1]=0; acc[i][2]=0; acc[i][3]=0; }

    for (int k0 = 0; k0 < K; k0 += 8){
        #pragma unroll
        for (int i = 0; i < 4; i++){
            int e = t + i*256;
            As[e & 7][e >> 3] = A[(size_t)(m0 + (e>>3))*K + k0 + (e&7)];
            Bs[e >> 7][e & 127] = B[(size_t)(k0 + (e>>7))*N + n0 + (e&127)];
        }
        __syncthreads();
        #pragma unroll
        for (int kk = 0; kk < 8; kk++){
            float4 a0 = *(const float4*)&As[kk][tr*4];
            float4 a1 = *(const float4*)&As[kk][64 + tr*4];
            ulonglong2 b0 = *(const ulonglong2*)&Bs[kk][tc*4];
            ulonglong2 b1 = *(const ulonglong2*)&Bs[kk][64 + tc*4];
            float a[8] = {a0.x,a0.y,a0.z,a0.w,a1.x,a1.y,a1.z,a1.w};
            #pragma unroll
            for (int i = 0; i < 8; i++){
                unsigned long long ap = pack2(a[i]);
                ffma2(acc[i][0], ap, b0.x); ffma2(acc[i][1], ap, b0.y);
                ffma2(acc[i][2], ap, b1.x); ffma2(acc[i][3], ap, b1.y);
            }
        }
        __syncthreads();
    }
    #pragma unroll
    for (int i = 0; i < 8; i++){
        int m = m0 + (i < 4 ? tr*4 + i : 64 + tr*4 + (i-4));
        float2 p0 = unpack2(acc[i][0]), p1 = unpack2(acc[i][1]);
        float2 p2 = unpack2(acc[i][2]), p3 = unpack2(acc[i][3]);
        float o[8] = {p0.x,p0.y,p1.x,p1.y,p2.x,p2.y,p3.x,p3.y};
        #pragma unroll
        for (int j = 0; j < 8; j++){
            if (EPI == 1) o[j] = (o[j] > 0.f) ? o[j] + 1.f : expf(o[j]);
            if (EPI == 2) o[j] = o[j] * scl;
        }
        float4 s0 = {o[0],o[1],o[2],o[3]}, s1 = {o[4],o[5],o[6],o[7]};
        *(float4*)&C[(size_t)m*N + n0 + tc*4]      = s0;
        *(float4*)&C[(size_t)m*N + n0 + 64 + tc*4] = s1;
    }
}

// ---- 3) KV[b,h,d,v] = sum_s Kp*Vn ; Ksum[b,h,d] = sum_s Kp ----
__global__ void attn_kv_kernel(){
    __shared__ __align__(16) float Ks[64][32];
    __shared__ __align__(16) float Vs[64][32];
    int t = threadIdx.x;
    int b = blockIdx.x >> 3, h = blockIdx.x & 7;
    int d = t >> 3, vg = (t & 7) * 4;
    float4 acc = {0.f,0.f,0.f,0.f};
    float ks = 0.f;
    for (int s0 = 0; s0 < 1024; s0 += 64){
        #pragma unroll
        for (int i = 0; i < 8; i++){
            int e = t + i*256;
            int s_ = e >> 5, d_ = e & 31;
            size_t gi = (size_t)(b*1024 + s0 + s_)*256 + h*32 + d_;
            Ks[s_][d_] = g_Kp[gi];
            Vs[s_][d_] = g_Vn[gi];
        }
        __syncthreads();
        #pragma unroll 8
        for (int s_ = 0; s_ < 64; s_++){
            float kd = Ks[s_][d];
            float4 v = *(const float4*)&Vs[s_][vg];
            acc.x += kd*v.x; acc.y += kd*v.y; acc.z += kd*v.z; acc.w += kd*v.w;
            ks += kd;
        }
        __syncthreads();
    }
    *(float4*)&g_KV[(size_t)((blockIdx.x*32 + d)*32 + vg)] = acc;
    if ((t & 7) == 0) g_Ksum[blockIdx.x*32 + d] = ks;
}

// ---- 4) msg = (Qp@KV) * L / (Qp.Ksum + eps) ----
__global__ void attn_msg_kernel(){
    __shared__ float KVs[8192];
    __shared__ float Ksums[256];
    int t = threadIdx.x;
    int p = blockIdx.x*8 + (t >> 5);   // 8 pixels/block, never crosses batch
    int lane = t & 31;
    int b = p >> 10;
    #pragma unroll
    for (int i = 0; i < 32; i++) KVs[t + i*256] = g_KV[b*8192 + t + i*256];
    if (t < 256) Ksums[t] = g_Ksum[b*256 + t];
    __syncthreads();
    #pragma unroll
    for (int h = 0; h < 8; h++){
        float qd = g_Qp[(size_t)p*256 + h*32 + lane];
        float zd = qd * Ksums[h*32 + lane];
        #pragma unroll
        for (int o = 16; o; o >>= 1) zd += __shfl_xor_sync(0xffffffffu, zd, o);
        float z = 1024.f / (zd + 1e-6f);
        float a = 0.f;
        #pragma unroll
        for (int dd = 0; dd < 32; dd++)
            a += __shfl_sync(0xffffffffu, qd, dd) * KVs[(h*32 + dd)*32 + lane];
        g_msg[(size_t)p*256 + h*32 + lane] = a * z;
    }
}

// ---- 5) MLP1: g_h = relu(x_nhwc @ W1[:256] + bilinear_up(T)) ----
__global__ __launch_bounds__(256, 2) void mlp1_kernel(const float* __restrict__ x,
                                                      const float* __restrict__ w1){
    __shared__ __align__(16) float As[8][132];
    __shared__ __align__(16) float Bs[8][128];
    __shared__ __align__(16) float Tsm[2][32][128];
    int t = threadIdx.x;
    int row = blockIdx.x;            // b*128 + hh
    int b = row >> 7, hh = row & 127;
    int n0 = blockIdx.y * 128;
    int tr = t >> 4, tc = t & 15;
    const float* xb = x + (size_t)b*4194304 + hh*128;
    unsigned long long acc[8][4];
    #pragma unroll
    for (int i = 0; i < 8; i++){ acc[i][0]=0; acc[i][1]=0; acc[i][2]=0; acc[i][3]=0; }

    for (int k0 = 0; k0 < 256; k0 += 8){
        #pragma unroll
        for (int i = 0; i < 4; i++){
            int e = t + i*256;
            int ma = e & 127, ka = e >> 7;
            As[ka][ma] = xb[(size_t)(k0+ka)*16384 + ma];     // A[ww][c]
            Bs[ka][ma] = w1[(size_t)(k0+ka)*512 + n0 + ma];
        }
        __syncthreads();
        #pragma unroll
        for (int kk = 0; kk < 8; kk++){
            float4 a0 = *(const float4*)&As[kk][tr*4];
            float4 a1 = *(const float4*)&As[kk][64 + tr*4];
            ulonglong2 b0 = *(const ulonglong2*)&Bs[kk][tc*4];
            ulonglong2 b1 = *(const ulonglong2*)&Bs[kk][64 + tc*4];
            float a[8] = {a0.x,a0.y,a0.z,a0.w,a1.x,a1.y,a1.z,a1.w};
            #pragma unroll
            for (int i = 0; i < 8; i++){
                unsigned long long ap = pack2(a[i]);
                ffma2(acc[i][0], ap, b0.x); ffma2(acc[i][1], ap, b0.y);
                ffma2(acc[i][2], ap, b1.x); ffma2(acc[i][3], ap, b1.y);
            }
        }
        __syncthreads();
    }

    // stage the two coarse-T rows needed by this image row (fixed y per block)
    float sy  = hh*0.25f - 0.375f;
    float y0f = floorf(sy);
    float fy  = sy - y0f;
    int y0 = max(0, min(31, (int)y0f));
    int y1 = max(0, min(31, (int)y0f + 1));
    #pragma unroll
    for (int i = 0; i < 32; i++){
        int e = t + i*256;
        int n_ = e & 127, xx = (e >> 7) & 31, yy = e >> 12;
        int ysrc = yy ? y1 : y0;
        Tsm[yy][xx][n_] = g_T[(size_t)((b*32 + ysrc)*32 + xx)*512 + n0 + n_];
    }
    __syncthreads();

    float* hout = g_h + (size_t)row*128*512 + n0;
    #pragma unroll
    for (int i = 0; i < 8; i++){
        int ww = (i < 4 ? tr*4 + i : 64 + tr*4 + (i-4));
        float sx  = ww*0.25f - 0.375f;
        float x0f = floorf(sx);
        float fx  = sx - x0f;
        int x0 = max(0, min(31, (int)x0f));
        int x1 = max(0, min(31, (int)x0f + 1));
        float2 p0 = unpack2(acc[i][0]), p1 = unpack2(acc[i][1]);
        float2 p2 = unpack2(acc[i][2]), p3 = unpack2(acc[i][3]);
        float v[8] = {p0.x,p0.y,p1.x,p1.y,p2.x,p2.y,p3.x,p3.y};
        float o[8];
        #pragma unroll
        for (int jj = 0; jj < 8; jj++){
            int n_ = (jj < 4 ? tc*4 + jj : 64 + tc*4 + (jj-4));
            float up = (1.f-fy)*((1.f-fx)*Tsm[0][x0][n_] + fx*Tsm[0][x1][n_])
                     +       fy*((1.f-fx)*Tsm[1][x0][n_] + fx*Tsm[1][x1][n_]);
            o[jj] = fmaxf(v[jj] + up, 0.f);
        }
        float4 s0 = {o[0],o[1],o[2],o[3]}, s1 = {o[4],o[5],o[6],o[7]};
        *(float4*)&hout[(size_t)ww*512 + tc*4]      = s0;
        *(float4*)&hout[(size_t)ww*512 + 64 + tc*4] = s1;
    }
}

// ---- 6) MLP2: out = x + LN(g_h @ W2), fused NCHW store ----
__global__ __launch_bounds__(256, 2) void mlp2_kernel(const float* __restrict__ x,
                                                      const float* __restrict__ w2,
                                                      const float* __restrict__ g2,
                                                      const float* __restrict__ b2,
                                                      float* __restrict__ out){
    __shared__ __align__(16) float As[8][68];
    __shared__ __align__(16) float Bs[8][256];
    int t = threadIdx.x;
    int w0  = (blockIdx.x & 1) * 64;
    int row = blockIdx.x >> 1;       // b*128 + hh
    int b = row >> 7, hh = row & 127;
    int tr = t >> 5, tc = t & 31;    // warp == tr; warp covers all 256 cols
    const float* hrow = g_h + ((size_t)row*128 + w0)*512;
    unsigned long long acc[8][4];
    #pragma unroll
    for (int i = 0; i < 8; i++){ acc[i][0]=0; acc[i][1]=0; acc[i][2]=0; acc[i][3]=0; }

    for (int k0 = 0; k0 < 512; k0 += 8){
        {
            int e = t;
            As[e & 7][e >> 3] = hrow[(size_t)(e>>3)*512 + k0 + (e&7)];
            e = t + 256;
            As[e & 7][e >> 3] = hrow[(size_t)(e>>3)*512 + k0 + (e&7)];
        }
        #pragma unroll
        for (int i = 0; i < 8; i++){
            int e = t + i*256;
            Bs[e >> 8][e & 255] = w2[(size_t)(k0 + (e>>8))*256 + (e&255)];
        }
        __syncthreads();
        #pragma unroll
        for (int kk = 0; kk < 8; kk++){
            float4 a0 = *(const float4*)&As[kk][tr*4];
            float4 a1 = *(const float4*)&As[kk][32 + tr*4];
            ulonglong2 bb0 = *(const ulonglong2*)&Bs[kk][tc*4];
            ulonglong2 bb1 = *(const ulonglong2*)&Bs[kk][128 + tc*4];
            float a[8] = {a0.x,a0.y,a0.z,a0.w,a1.x,a1.y,a1.z,a1.w};
            #pragma unroll
            for (int i = 0; i < 8; i++){
                unsigned long long ap = pack2(a[i]);
                ffma2(acc[i][0], ap, bb0.x); ffma2(acc[i][1], ap, bb0.y);
                ffma2(acc[i][2], ap, bb1.x); ffma2(acc[i][3], ap, bb1.y);
            }
        }
        __syncthreads();
    }

    // LN stats per pixel (warp reduction over the 256 cols it owns)
    float s[8], sq[8];
    #pragma unroll
    for (int i = 0; i < 8; i++){ s[i]=0.f; sq[i]=0.f; }
    #pragma unroll
    for (int i = 0; i < 8; i++)
        #pragma unroll
        for (int j = 0; j < 4; j++){
            float2 p = unpack2(acc[i][j]);
            s[i]  += p.x + p.y;
            sq[i] += p.x*p.x + p.y*p.y;
        }
    #pragma unroll
    for (int o = 16; o; o >>= 1)
        #pragma unroll
        for (int i = 0; i < 8; i++){
            s[i]  += __shfl_xor_sync(0xffffffffu, s[i],  o);
            sq[i] += __shfl_xor_sync(0xffffffffu, sq[i], o);
        }
    float mean[8], rstd[8];
    #pragma unroll
    for (int i = 0; i < 8; i++){
        mean[i] = s[i] * (1.f/256.f);
        rstd[i] = rsqrtf(sq[i]*(1.f/256.f) - mean[i]*mean[i] + 1e-5f);
    }

    #pragma unroll
    for (int jj = 0; jj < 8; jj++){
        int n  = (jj < 4 ? tc*4 + jj : 128 + tc*4 + (jj-4));
        int pi = (jj < 4 ? (jj >> 1) : 2 + ((jj-4) >> 1));
        int half = jj & 1;
        float gn = g2[n], bn = b2[n];
        size_t base = ((size_t)(b*256 + n)*128 + hh)*128 + w0;
        float4 x0v = *(const float4*)&x[base + tr*4];
        float4 x1v = *(const float4*)&x[base + 32 + tr*4];
        float vv[8];
        #pragma unroll
        for (int i = 0; i < 8; i++){
            float2 p = unpack2(acc[i][pi]);
            float val = half ? p.y : p.x;
            vv[i] = (val - mean[i]) * rstd[i] * gn + bn;
        }
        float4 o0 = {x0v.x + vv[0], x0v.y + vv[1], x0v.z + vv[2], x0v.w + vv[3]};
        float4 o1 = {x1v.x + vv[4], x1v.y + vv[5], x1v.z + vv[6], x1v.w + vv[7]};
        *(float4*)&out[base + tr*4]      = o0;
        *(float4*)&out[base + 32 + tr*4] = o1;
    }
}

// ---- launch ----
extern "C" void kernel_launch(void* const* d_in, const int* in_sizes, int n_in,
                              void* d_out, int out_size){
    const float* x   = (const float*)d_in[0];
    const float* src = (const float*)d_in[1];
    const float* n1g = (const float*)d_in[2];
    const float* n1b = (const float*)d_in[3];
    const float* wq  = (const float*)d_in[4];
    const float* wk  = (const float*)d_in[5];
    const float* wv  = (const float*)d_in[6];
    const float* wm  = (const float*)d_in[7];
    const float* w1  = (const float*)d_in[8];
    const float* w2  = (const float*)d_in[9];
    const float* n2g = (const float*)d_in[10];
    const float* n2b = (const float*)d_in[11];
    float* out = (float*)d_out;

    float *p_qin, *p_sin, *p_Qp, *p_Kp, *p_Vn, *p_msg, *p_msg2, *p_T;
    cudaGetSymbolAddress((void**)&p_qin,  g_qin);
    cudaGetSymbolAddress((void**)&p_sin,  g_sin);
    cudaGetSymbolAddress((void**)&p_Qp,   g_Qp);
    cudaGetSymbolAddress((void**)&p_Kp,   g_Kp);
    cudaGetSymbolAddress((void**)&p_Vn,   g_Vn);
    cudaGetSymbolAddress((void**)&p_msg,  g_msg);
    cudaGetSymbolAddress((void**)&p_msg2, g_msg2);
    cudaGetSymbolAddress((void**)&p_T,    g_T);

    pool_kernel<<<dim3(4096,2), 256>>>(x, src);
    ln1_kernel<<<dim3(512,2), 256>>>(n1g, n1b);
    gemm128<1><<<dim3(32,2), 256>>>(p_qin, wq, p_Qp, 256, 256, 0.f);
    gemm128<1><<<dim3(32,2), 256>>>(p_sin, wk, p_Kp, 256, 256, 0.f);
    gemm128<2><<<dim3(32,2), 256>>>(p_sin, wv, p_Vn, 256, 256, 1.f/1024.f);
    attn_kv_kernel<<<32, 256>>>();
    attn_msg_kernel<<<512, 256>>>();
    gemm128<0><<<dim3(32,2), 256>>>(p_msg, wm, p_msg2, 256, 256, 0.f);
    gemm128<0><<<dim3(32,4), 256>>>(p_msg2, w1 + 256*512, p_T, 256, 512, 0.f);
    mlp1_kernel<<<dim3(512,4), 256>>>(x, w1);
    mlp2_kernel<<<1024, 256>>>(x, w2, n2g, n2b, out);
}